// round 1
// baseline (speedup 1.0000x reference)
#include <cuda_runtime.h>
#include <cuda_bf16.h>

// PEPS 6x6, D=4, phys=2, batch=1024.
// Row-sweep exact contraction: V over 6 vertical bonds (4^6), absorb one site
// at a time. Snake ordering (row0 L->R, row1 R->L, ...) keeps layouts aligned
// with no transposes. One CTA per configuration.
//
// Generic step (site (i, jc), sweep-direction-dependent axis roles):
//   Input  Win: [rin (Rin), dprev (Pd), u (ud), urest (Pu)]
//   A     : [k = rin*ud + u][n = rout*dd + d]   (staged per row in SMEM)
//   Output Wout: [n (N)][m (F = Pd*Pu)]  with addr = n*F + dp*Pu + ur
// Interior rows (i=1..4): F = 1024 for every step, S_rin = 4096, S_u = Pu.

#define NT 512

__device__ __forceinline__ void step_generic(
    const float* __restrict__ Win, float* __restrict__ Wout,
    const float* __restrict__ A, int F, int K, int N,
    int Pu, int ud, int Srin, int tid)
{
    int total = N * F;
    for (int o = tid; o < total; o += NT) {
        int n = o / F;
        int m = o - n * F;
        int dp = m / Pu;
        int ur = m - dp * Pu;
        int inb = dp * ud * Pu + ur;
        float s = 0.f;
        for (int k = 0; k < K; ++k) {
            int rin = k / ud;
            int u = k - rin * ud;
            s = fmaf(Win[inb + rin * Srin + u * Pu], A[k * N + n], s);
        }
        Wout[n * F + m] = s;
    }
}

// Fast path for interior rows: F=1024, ud=4, S_rin=4096, S_u = 1<<PSH.
// 512 threads split into 2 n-groups of NG outputs; each thread handles
// 4 m-slots (m = t, t+256, t+512, t+768). 4m x NG-n register blocking:
// per k: 4 input LDS + NG broadcast-A LDS + 4*NG FMA  -> ~2.7 FMA/LDS.
template <int K, int NG, int NTOT, int PSH>
__device__ __forceinline__ void step_fast(
    const float* __restrict__ Win, float* __restrict__ Wout,
    const float* __restrict__ A, int tid)
{
    const int g = tid >> 8;       // n-group (0..1)
    const int t = tid & 255;      // m lane
    const float* Ag = A + g * NG;

    float acc[4][NG];
#pragma unroll
    for (int c = 0; c < 4; ++c)
#pragma unroll
        for (int n = 0; n < NG; ++n) acc[c][n] = 0.f;

    int inb[4];
#pragma unroll
    for (int c = 0; c < 4; ++c) {
        int m = t + c * 256;
        int dp = m >> PSH;
        int ur = m & ((1 << PSH) - 1);
        inb[c] = (dp << (PSH + 2)) + ur;   // dp * 4 * Pu + ur
    }

#pragma unroll
    for (int k = 0; k < K; ++k) {
        const int rin = k >> 2;
        const int u = k & 3;
        const int off = rin * 4096 + (u << PSH);
        float xv[4];
#pragma unroll
        for (int c = 0; c < 4; ++c) xv[c] = Win[inb[c] + off];
#pragma unroll
        for (int n = 0; n < NG; ++n) {
            const float a = Ag[k * NTOT + n];
#pragma unroll
            for (int c = 0; c < 4; ++c) acc[c][n] = fmaf(xv[c], a, acc[c][n]);
        }
    }

#pragma unroll
    for (int n = 0; n < NG; ++n) {
#pragma unroll
        for (int c = 0; c < 4; ++c) {
            Wout[(g * NG + n) * 1024 + t + c * 256] = acc[c][n];
        }
    }
}

__global__ __launch_bounds__(NT, 1)
void peps_amp_kernel(const int* __restrict__ x, const float* __restrict__ T,
                     float* __restrict__ out)
{
    extern __shared__ float smem[];
    float* W0 = smem;                 // 16384
    float* W1 = smem + 16384;         // 16384
    float* As = smem + 32768;         // 6 * 256
    int* spins = (int*)(smem + 32768 + 1536);   // 36

    const int b = blockIdx.x;
    const int tid = threadIdx.x;

    if (tid < 36) spins[tid] = x[b * 36 + tid];
    if (tid == 0) W0[0] = 1.0f;       // initial boundary vector (all up-bonds = index 0)
    __syncthreads();

    float* bufs[2] = { W0, W1 };
    int cur = 0;

    for (int i = 0; i < 6; ++i) {
        const int ud = (i == 0) ? 1 : 4;   // up-bond dim this row
        const int dd = (i == 5) ? 1 : 4;   // down-bond dim this row
        const bool l2r = ((i & 1) == 0);   // snake direction

        // Stage the 6 site tensors of this row: As[st][k*N + n],
        // k = rin*ud + u, n = rout*dd + d. Axis (up,right,down,left) roles:
        // L->R: in-bond = left, out-bond = right.  R->L: in = right, out = left.
        for (int st = 0; st < 6; ++st) {
            const int Rin  = (st == 0) ? 1 : 4;
            const int Rout = (st == 5) ? 1 : 4;
            const int K = ud * Rin;
            const int N = Rout * dd;
            const int jc = l2r ? st : (5 - st);
            const int s = spins[i * 6 + jc];
            const float* Tb = T + (size_t)((i * 6 + jc) * 2 + s) * 256;
            for (int idx = tid; idx < K * N; idx += NT) {
                int k = idx / N, n = idx - k * N;
                int rin = k / ud, u = k - rin * ud;
                int rout = n / dd, d = n - rout * dd;
                int r = l2r ? rout : rin;
                int l = l2r ? rin : rout;
                As[st * 256 + idx] = Tb[u * 64 + r * 16 + d * 4 + l];
            }
        }
        __syncthreads();

        for (int st = 0; st < 6; ++st) {
            const float* Win = bufs[cur];
            float* Wout = bufs[cur ^ 1];
            const float* A = As + st * 256;

            if (ud == 4 && dd == 4) {
                // interior rows: F = 1024 always
                switch (st) {
                    case 0: step_fast<4, 8, 16, 10>(Win, Wout, A, tid); break;
                    case 1: step_fast<16, 8, 16, 8>(Win, Wout, A, tid); break;
                    case 2: step_fast<16, 8, 16, 6>(Win, Wout, A, tid); break;
                    case 3: step_fast<16, 8, 16, 4>(Win, Wout, A, tid); break;
                    case 4: step_fast<16, 8, 16, 2>(Win, Wout, A, tid); break;
                    default: step_fast<16, 2, 4, 0>(Win, Wout, A, tid); break;
                }
            } else {
                const int Rin  = (st == 0) ? 1 : 4;
                const int Rout = (st == 5) ? 1 : 4;
                const int K = ud * Rin;
                const int N = Rout * dd;
                const int Pd = (dd == 1) ? 1 : (1 << (2 * st));
                const int Pu = (ud == 1) ? 1 : (1 << (2 * (5 - st)));
                step_generic(Win, Wout, A, Pd * Pu, K, N, Pu, ud,
                             Pd * ud * Pu, tid);
            }
            cur ^= 1;
            __syncthreads();
        }
    }

    if (tid == 0) out[b] = bufs[cur][0];
}

extern "C" void kernel_launch(void* const* d_in, const int* in_sizes, int n_in,
                              void* d_out, int out_size)
{
    // metadata order is {x, T}; detect defensively by element counts.
    const int T_ELEMS = 6 * 6 * 2 * 4 * 4 * 4 * 4;   // 73728
    const int* x;
    const float* T;
    if (in_sizes[0] == T_ELEMS) {
        T = (const float*)d_in[0];
        x = (const int*)d_in[1];
    } else {
        x = (const int*)d_in[0];
        T = (const float*)d_in[1];
    }

    const int smem_bytes = (16384 + 16384 + 6 * 256 + 64) * (int)sizeof(float);
    cudaFuncSetAttribute(peps_amp_kernel,
                         cudaFuncAttributeMaxDynamicSharedMemorySize, smem_bytes);

    peps_amp_kernel<<<out_size, NT, smem_bytes>>>(x, T, (float*)d_out);
}